// round 2
// baseline (speedup 1.0000x reference)
#include <cuda_runtime.h>
#include <cstdint>

// Problem constants
#define NQ     32768
#define SGRID  32768
#define NEDGE  262144
#define C      192
#define C2     384
#define TILE   64
#define NTHR   384
#define KT     32
#define SROW   66   // smem row stride (floats) for [feature][edge] tiles
#define IDXMASK 32767

// Scratch (device globals; no allocation allowed). 16B-aligned for LDG/STG.128.
__device__ __align__(16) float g_xf[(size_t)SGRID * C];
__device__ __align__(16) float g_qe[(size_t)NQ * C];
__device__ __align__(16) float g_seg[(size_t)NQ * C];
__device__ int   g_cnt[NQ];
__device__ int   g_edge64;   // 1 if edges are int64, 0 if int32

typedef unsigned long long u64;

__device__ __forceinline__ u64 pk2(float lo, float hi) {
    u64 r; asm("mov.b64 %0,{%1,%2};" : "=l"(r) : "f"(lo), "f"(hi)); return r;
}
__device__ __forceinline__ void upk2(u64 v, float& lo, float& hi) {
    asm("mov.b64 {%0,%1},%2;" : "=f"(lo), "=f"(hi) : "l"(v));
}
// Packed fp32x2 FMA (Blackwell): d = a*b + c on both 32-bit lanes
__device__ __forceinline__ u64 fma2(u64 a, u64 b, u64 c) {
    u64 d; asm("fma.rn.f32x2 %0,%1,%2,%3;" : "=l"(d) : "l"(a), "l"(b), "l"(c)); return d;
}

__device__ __forceinline__ float gelu_f(float x) {
    return 0.5f * x * (1.0f + erff(x * 0.7071067811865476f));
}

// Fetch edge e -> (qidx, gidx) under either dtype interpretation.
__device__ __forceinline__ void load_edge(const void* Eg, int e, int& q, int& g) {
    if (g_edge64) {
        const long long* E = (const long long*)Eg;
        q = (int)E[2 * (size_t)e] & IDXMASK;
        g = (int)E[2 * (size_t)e + 1] & IDXMASK;
    } else {
        const int* E = (const int*)Eg;
        q = E[2 * (size_t)e] & IDXMASK;
        g = E[2 * (size_t)e + 1] & IDXMASK;
    }
}

// Detect edge dtype: int64 values < 32768 have zero high words at odd int32
// positions; int32 layout puts gidx (random 0..32767) there.
__global__ void k_detect(const int* __restrict__ E32) {
    if (threadIdx.x == 0) {
        int mode = 1;
        for (int i = 1; i < 128; i += 2)
            if (E32[i] != 0) { mode = 0; break; }
        g_edge64 = mode;
    }
}

// One dense layer on a 64-sample tile held in smem ([feature][edge] layout).
// src: [KIN][SROW] smem, dst: [NTOT][SROW] smem, wt: KT*192 floats smem staging.
// W is row-major [KIN][NTOT] in gmem. 384 threads: tx=tid%48 (4 cols each of a
// 192-col chunk), ty=tid/48 (4 edge-pairs each). Caller syncs around the call.
template<int KIN, int NTOT, bool DOGELU>
__device__ __forceinline__ void layer_mlp(const float* __restrict__ Wg,
                                          const float* __restrict__ bg,
                                          const float* src, float* dst,
                                          float* wt, int tid)
{
    const int tx = tid % 48;
    const int ty = tid / 48;
    for (int nc = 0; nc < NTOT; nc += 192) {
        u64 acc[4][4];
        #pragma unroll
        for (int p = 0; p < 4; p++)
            #pragma unroll
            for (int ci = 0; ci < 4; ci++) acc[p][ci] = 0ull;

        for (int kt0 = 0; kt0 < KIN; kt0 += KT) {
            // Stage W tile [KT][192] (coalesced float4)
            #pragma unroll
            for (int j = 0; j < 4; j++) {
                int f  = tid + j * NTHR;          // float4 id, 0..1535
                int r  = f / 48;
                int c4 = f % 48;
                float4 v = *(const float4*)&Wg[(size_t)(kt0 + r) * NTOT + nc + c4 * 4];
                *(float4*)&wt[r * 192 + c4 * 4] = v;
            }
            __syncthreads();
            #pragma unroll
            for (int kk = 0; kk < KT; kk++) {
                const float* srow = src + (kt0 + kk) * SROW + 8 * ty;
                u64 a0 = *(const u64*)&srow[0];
                u64 a1 = *(const u64*)&srow[2];
                u64 a2 = *(const u64*)&srow[4];
                u64 a3 = *(const u64*)&srow[6];
                float4 bv = *(const float4*)&wt[kk * 192 + tx * 4];
                u64 b0 = pk2(bv.x, bv.x);
                u64 b1 = pk2(bv.y, bv.y);
                u64 b2 = pk2(bv.z, bv.z);
                u64 b3 = pk2(bv.w, bv.w);
                acc[0][0] = fma2(a0, b0, acc[0][0]);
                acc[0][1] = fma2(a0, b1, acc[0][1]);
                acc[0][2] = fma2(a0, b2, acc[0][2]);
                acc[0][3] = fma2(a0, b3, acc[0][3]);
                acc[1][0] = fma2(a1, b0, acc[1][0]);
                acc[1][1] = fma2(a1, b1, acc[1][1]);
                acc[1][2] = fma2(a1, b2, acc[1][2]);
                acc[1][3] = fma2(a1, b3, acc[1][3]);
                acc[2][0] = fma2(a2, b0, acc[2][0]);
                acc[2][1] = fma2(a2, b1, acc[2][1]);
                acc[2][2] = fma2(a2, b2, acc[2][2]);
                acc[2][3] = fma2(a2, b3, acc[2][3]);
                acc[3][0] = fma2(a3, b0, acc[3][0]);
                acc[3][1] = fma2(a3, b1, acc[3][1]);
                acc[3][2] = fma2(a3, b2, acc[3][2]);
                acc[3][3] = fma2(a3, b3, acc[3][3]);
            }
            __syncthreads();
        }
        // Epilogue: bias (+gelu), store transposed tile rows nc..nc+191
        #pragma unroll
        for (int ci = 0; ci < 4; ci++) {
            int col = nc + tx * 4 + ci;
            float bb = bg[col];
            #pragma unroll
            for (int p = 0; p < 4; p++) {
                float lo, hi;
                upk2(acc[p][ci], lo, hi);
                lo += bb; hi += bb;
                if (DOGELU) { lo = gelu_f(lo); hi = gelu_f(hi); }
                *(u64*)&dst[(size_t)col * SROW + 8 * ty + 2 * p] = pk2(lo, hi);
            }
        }
    }
}

// ---------------- sincos query embedding ----------------
__global__ void k_embed(const float* __restrict__ qp) {
    int q = blockIdx.x;
    int t = threadIdx.x;           // 96 threads: d = t/32, j = t%32
    int d = t >> 5, j = t & 31;
    float c = qp[q * 3 + d];
    float omega = powf(10000.0f, -(float)(2 * j) / 64.0f);
    float a = c * omega;
    float s, co;
    sincosf(a, &s, &co);
    g_qe[(size_t)q * C + d * 64 + j]      = s;
    g_qe[(size_t)q * C + d * 64 + 32 + j] = co;
}

// ---------------- projection GEMM: xf = x @ proj_w + proj_b ----------------
__global__ void __launch_bounds__(NTHR, 1) k_proj(const float* __restrict__ x,
                                                  const float* __restrict__ W,
                                                  const float* __restrict__ b)
{
    extern __shared__ float sm[];
    float* bufA = sm;                    // [192][SROW]
    float* bufB = bufA + C * SROW;       // [192][SROW]
    float* wt   = bufB + C * SROW;       // KT*192
    int tid = threadIdx.x;
    int r0 = blockIdx.x * TILE;
    {
        int e = tid / 6, t2 = tid % 6;   // 32 floats per thread
        const float* src = x + (size_t)(r0 + e) * C + t2 * 32;
        int cbase = t2 * 32;
        #pragma unroll
        for (int i = 0; i < 8; i++) {
            float4 v = *(const float4*)(src + i * 4);
            int c = cbase + i * 4;
            bufA[(c + 0) * SROW + e] = v.x;
            bufA[(c + 1) * SROW + e] = v.y;
            bufA[(c + 2) * SROW + e] = v.z;
            bufA[(c + 3) * SROW + e] = v.w;
        }
    }
    __syncthreads();
    layer_mlp<C, C, false>(W, b, bufA, bufB, wt, tid);
    __syncthreads();
    // Write back row-major
    #pragma unroll
    for (int j = 0; j < 32; j++) {
        int f = tid + j * NTHR;          // 0..12287
        int e = f / C, c = f % C;
        g_xf[(size_t)(r0 + e) * C + c] = bufB[(size_t)c * SROW + e];
    }
}

// ---------------- zero accumulators ----------------
__global__ void k_zero() {
    int idx = blockIdx.x * blockDim.x + threadIdx.x;
    int stride = gridDim.x * blockDim.x;
    for (int i = idx; i < NQ * C; i += stride) g_seg[i] = 0.0f;
    for (int i = idx; i < NQ; i += stride) g_cnt[i] = 0;
}

// ---------------- fused edge MLP + segment sum ----------------
__global__ void __launch_bounds__(NTHR, 1) k_edges(const void* __restrict__ Eg,
    const float* __restrict__ W0, const float* __restrict__ b0,
    const float* __restrict__ W1, const float* __restrict__ b1,
    const float* __restrict__ W2, const float* __restrict__ b2)
{
    extern __shared__ float sm[];
    float* bufA = sm;                     // [384][SROW]
    float* bufB = bufA + C2 * SROW;       // [384][SROW]
    float* wt   = bufB + C2 * SROW;       // KT*192
    int* qs = (int*)(wt + KT * 192);      // [64]
    int tid = threadIdx.x;
    int e0 = blockIdx.x * TILE;
    // Gather: 6 threads/edge, 64 floats each (first 192 cols = xf[g], next 192 = qe[q])
    {
        int e = tid / 6, t2 = tid % 6;
        int q, g;
        load_edge(Eg, e0 + e, q, g);
        if (t2 == 0) qs[e] = q;
        const float* src = (t2 < 3) ? (g_xf + (size_t)g * C + t2 * 64)
                                    : (g_qe + (size_t)q * C + (t2 - 3) * 64);
        int cbase = t2 * 64;
        #pragma unroll
        for (int i = 0; i < 16; i++) {
            float4 v = *(const float4*)(src + i * 4);
            int c = cbase + i * 4;
            bufA[(c + 0) * SROW + e] = v.x;
            bufA[(c + 1) * SROW + e] = v.y;
            bufA[(c + 2) * SROW + e] = v.z;
            bufA[(c + 3) * SROW + e] = v.w;
        }
    }
    __syncthreads();
    layer_mlp<C2, C2, true >(W0, b0, bufA, bufB, wt, tid);
    __syncthreads();
    layer_mlp<C2, C2, true >(W1, b1, bufB, bufA, wt, tid);
    __syncthreads();
    layer_mlp<C2, C,  false>(W2, b2, bufA, bufB, wt, tid);
    __syncthreads();
    // Segment-sum: qidx is globally sorted -> runs are contiguous within tile.
    if (tid < C) {
        int c = tid;
        int cur = qs[0];
        float s = bufB[(size_t)c * SROW + 0];
        for (int e = 1; e < TILE; e++) {
            int q = qs[e];
            float v = bufB[(size_t)c * SROW + e];
            if (q == cur) s += v;
            else { atomicAdd(&g_seg[(size_t)cur * C + c], s); cur = q; s = v; }
        }
        atomicAdd(&g_seg[(size_t)cur * C + c], s);
    } else if (tid == C) {
        int cur = qs[0]; int n = 1;
        for (int e = 1; e < TILE; e++) {
            int q = qs[e];
            if (q == cur) n++;
            else { atomicAdd(&g_cnt[cur], n); cur = q; n = 1; }
        }
        atomicAdd(&g_cnt[cur], n);
    }
}

// ---------------- prediction head ----------------
__global__ void __launch_bounds__(NTHR, 1) k_pred(const float* __restrict__ Wp0,
                                                  const float* __restrict__ bp0,
                                                  const float* __restrict__ Wp1,
                                                  const float* __restrict__ bp1,
                                                  float* __restrict__ out)
{
    extern __shared__ float sm[];
    float* bufA = sm;
    float* bufB = bufA + C * SROW;
    float* wt   = bufB + C * SROW;
    int tid = threadIdx.x;
    int q0 = blockIdx.x * TILE;
    {
        int e = tid / 6, t2 = tid % 6;
        int q = q0 + e;
        float inv = 1.0f / fmaxf((float)g_cnt[q], 1.0f);
        const float* src = g_seg + (size_t)q * C + t2 * 32;
        int cbase = t2 * 32;
        #pragma unroll
        for (int i = 0; i < 8; i++) {
            float4 v = *(const float4*)(src + i * 4);
            int c = cbase + i * 4;
            bufA[(c + 0) * SROW + e] = v.x * inv;
            bufA[(c + 1) * SROW + e] = v.y * inv;
            bufA[(c + 2) * SROW + e] = v.z * inv;
            bufA[(c + 3) * SROW + e] = v.w * inv;
        }
    }
    __syncthreads();
    layer_mlp<C, C, true>(Wp0, bp0, bufA, bufB, wt, tid);
    __syncthreads();
    if (tid < 256) {
        int q = tid >> 2, o = tid & 3;
        float s = bp1[o];
        #pragma unroll 8
        for (int k = 0; k < C; k++)
            s += bufB[(size_t)k * SROW + q] * Wp1[k * 4 + o];
        out[(size_t)(q0 + q) * 4 + o] = s;
    }
}

extern "C" void kernel_launch(void* const* d_in, const int* in_sizes, int n_in,
                              void* d_out, int out_size)
{
    const float* x       = (const float*)d_in[0];
    const float* qp      = (const float*)d_in[1];
    const void*  E       = d_in[2];
    const float* proj_w  = (const float*)d_in[3];
    const float* proj_b  = (const float*)d_in[4];
    const float* m0w     = (const float*)d_in[5];
    const float* m0b     = (const float*)d_in[6];
    const float* m1w     = (const float*)d_in[7];
    const float* m1b     = (const float*)d_in[8];
    const float* m2w     = (const float*)d_in[9];
    const float* m2b     = (const float*)d_in[10];
    const float* p0w     = (const float*)d_in[11];
    const float* p0b     = (const float*)d_in[12];
    const float* p1w     = (const float*)d_in[13];
    const float* p1b     = (const float*)d_in[14];
    float* out = (float*)d_out;

    const int SM_EDGE  = (2 * C2 * SROW + KT * 192) * 4 + TILE * 4;  // 227,584 B
    const int SM_SMALL = (2 * C * SROW + KT * 192) * 4;              // 125,952 B

    cudaFuncSetAttribute(k_edges, cudaFuncAttributeMaxDynamicSharedMemorySize, SM_EDGE);
    cudaFuncSetAttribute(k_proj,  cudaFuncAttributeMaxDynamicSharedMemorySize, SM_SMALL);
    cudaFuncSetAttribute(k_pred,  cudaFuncAttributeMaxDynamicSharedMemorySize, SM_SMALL);

    k_detect<<<1, 32>>>((const int*)E);
    k_embed<<<NQ, 96>>>(qp);
    k_proj<<<SGRID / TILE, NTHR, SM_SMALL>>>(x, proj_w, proj_b);
    k_zero<<<2048, 256>>>();
    k_edges<<<NEDGE / TILE, NTHR, SM_EDGE>>>(E, m0w, m0b, m1w, m1b, m2w, m2b);
    k_pred<<<NQ / TILE, NTHR, SM_SMALL>>>(p0w, p0b, p1w, p1b, out);
}

// round 3
// speedup vs baseline: 1.6140x; 1.6140x over previous
#include <cuda_runtime.h>
#include <cstdint>

// Problem constants
#define NQ     32768
#define SGRID  32768
#define NEDGE  262144
#define C      192
#define C2     384
#define TILE   64
#define NTHR   384
#define KT     32
#define SROW   66   // smem row stride (floats) for [feature][edge] tiles
#define IDXMASK 32767

// Scratch (device globals; no allocation allowed). 16B-aligned for LDG/STG.128.
__device__ __align__(16) float g_xf[(size_t)SGRID * C];
__device__ __align__(16) float g_qe[(size_t)NQ * C];
__device__ __align__(16) float g_seg[(size_t)NQ * C];
__device__ int   g_cnt[NQ];
__device__ int   g_edge64;   // 1 if edges are int64, 0 if int32

typedef unsigned long long u64;

__device__ __forceinline__ u64 pk2(float lo, float hi) {
    u64 r; asm("mov.b64 %0,{%1,%2};" : "=l"(r) : "f"(lo), "f"(hi)); return r;
}
__device__ __forceinline__ void upk2(u64 v, float& lo, float& hi) {
    asm("mov.b64 {%0,%1},%2;" : "=f"(lo), "=f"(hi) : "l"(v));
}
// Packed fp32x2 FMA (Blackwell): d = a*b + c on both 32-bit lanes
__device__ __forceinline__ u64 fma2(u64 a, u64 b, u64 c) {
    u64 d; asm("fma.rn.f32x2 %0,%1,%2,%3;" : "=l"(d) : "l"(a), "l"(b), "l"(c)); return d;
}

__device__ __forceinline__ float gelu_f(float x) {
    return 0.5f * x * (1.0f + erff(x * 0.7071067811865476f));
}

// Fetch edge e -> (qidx, gidx) under either dtype interpretation.
__device__ __forceinline__ void load_edge(const void* Eg, int e, int& q, int& g) {
    if (g_edge64) {
        const long long* E = (const long long*)Eg;
        q = (int)E[2 * (size_t)e] & IDXMASK;
        g = (int)E[2 * (size_t)e + 1] & IDXMASK;
    } else {
        const int* E = (const int*)Eg;
        q = E[2 * (size_t)e] & IDXMASK;
        g = E[2 * (size_t)e + 1] & IDXMASK;
    }
}

// Detect edge dtype: int64 values < 32768 have zero high words at odd int32
// positions; int32 layout puts gidx (random 0..32767) there.
__global__ void k_detect(const int* __restrict__ E32) {
    if (threadIdx.x == 0) {
        int mode = 1;
        for (int i = 1; i < 128; i += 2)
            if (E32[i] != 0) { mode = 0; break; }
        g_edge64 = mode;
    }
}

// One dense layer on a 64-sample tile held in smem ([feature][edge] layout).
// src: [KIN][SROW] smem, dst: [NTOT][SROW] smem, wt: KT*192 floats smem staging.
// W is row-major [KIN][NTOT] in gmem. 384 threads: tx=tid%48 (4 cols each of a
// 192-col chunk), ty=tid/48 (4 edge-pairs each). Caller syncs around the call.
template<int KIN, int NTOT, bool DOGELU>
__device__ __forceinline__ void layer_mlp(const float* __restrict__ Wg,
                                          const float* __restrict__ bg,
                                          const float* src, float* dst,
                                          float* wt, int tid)
{
    const int tx = tid % 48;
    const int ty = tid / 48;
    for (int nc = 0; nc < NTOT; nc += 192) {
        u64 acc[4][4];
        #pragma unroll
        for (int p = 0; p < 4; p++)
            #pragma unroll
            for (int ci = 0; ci < 4; ci++) acc[p][ci] = 0ull;

        for (int kt0 = 0; kt0 < KIN; kt0 += KT) {
            // Stage W tile [KT][192] (coalesced float4)
            #pragma unroll
            for (int j = 0; j < 4; j++) {
                int f  = tid + j * NTHR;          // float4 id, 0..1535
                int r  = f / 48;
                int c4 = f % 48;
                float4 v = *(const float4*)&Wg[(size_t)(kt0 + r) * NTOT + nc + c4 * 4];
                *(float4*)&wt[r * 192 + c4 * 4] = v;
            }
            __syncthreads();
            #pragma unroll
            for (int kk = 0; kk < KT; kk++) {
                const float* srow = src + (kt0 + kk) * SROW + 8 * ty;
                u64 a0 = *(const u64*)&srow[0];
                u64 a1 = *(const u64*)&srow[2];
                u64 a2 = *(const u64*)&srow[4];
                u64 a3 = *(const u64*)&srow[6];
                float4 bv = *(const float4*)&wt[kk * 192 + tx * 4];
                u64 b0 = pk2(bv.x, bv.x);
                u64 b1 = pk2(bv.y, bv.y);
                u64 b2 = pk2(bv.z, bv.z);
                u64 b3 = pk2(bv.w, bv.w);
                acc[0][0] = fma2(a0, b0, acc[0][0]);
                acc[0][1] = fma2(a0, b1, acc[0][1]);
                acc[0][2] = fma2(a0, b2, acc[0][2]);
                acc[0][3] = fma2(a0, b3, acc[0][3]);
                acc[1][0] = fma2(a1, b0, acc[1][0]);
                acc[1][1] = fma2(a1, b1, acc[1][1]);
                acc[1][2] = fma2(a1, b2, acc[1][2]);
                acc[1][3] = fma2(a1, b3, acc[1][3]);
                acc[2][0] = fma2(a2, b0, acc[2][0]);
                acc[2][1] = fma2(a2, b1, acc[2][1]);
                acc[2][2] = fma2(a2, b2, acc[2][2]);
                acc[2][3] = fma2(a2, b3, acc[2][3]);
                acc[3][0] = fma2(a3, b0, acc[3][0]);
                acc[3][1] = fma2(a3, b1, acc[3][1]);
                acc[3][2] = fma2(a3, b2, acc[3][2]);
                acc[3][3] = fma2(a3, b3, acc[3][3]);
            }
            __syncthreads();
        }
        // Epilogue: bias (+gelu), store transposed tile rows nc..nc+191
        #pragma unroll
        for (int ci = 0; ci < 4; ci++) {
            int col = nc + tx * 4 + ci;
            float bb = bg[col];
            #pragma unroll
            for (int p = 0; p < 4; p++) {
                float lo, hi;
                upk2(acc[p][ci], lo, hi);
                lo += bb; hi += bb;
                if (DOGELU) { lo = gelu_f(lo); hi = gelu_f(hi); }
                *(u64*)&dst[(size_t)col * SROW + 8 * ty + 2 * p] = pk2(lo, hi);
            }
        }
    }
}

// ---------------- sincos query embedding ----------------
__global__ void k_embed(const float* __restrict__ qp) {
    int q = blockIdx.x;
    int t = threadIdx.x;           // 96 threads: d = t/32, j = t%32
    int d = t >> 5, j = t & 31;
    float c = qp[q * 3 + d];
    float omega = powf(10000.0f, -(float)(2 * j) / 64.0f);
    float a = c * omega;
    float s, co;
    sincosf(a, &s, &co);
    g_qe[(size_t)q * C + d * 64 + j]      = s;
    g_qe[(size_t)q * C + d * 64 + 32 + j] = co;
}

// ---------------- projection GEMM: xf = x @ proj_w + proj_b ----------------
__global__ void __launch_bounds__(NTHR, 1) k_proj(const float* __restrict__ x,
                                                  const float* __restrict__ W,
                                                  const float* __restrict__ b)
{
    extern __shared__ float sm[];
    float* bufA = sm;                    // [192][SROW]
    float* bufB = bufA + C * SROW;       // [192][SROW]
    float* wt   = bufB + C * SROW;       // KT*192
    int tid = threadIdx.x;
    int r0 = blockIdx.x * TILE;
    {
        int e = tid / 6, t2 = tid % 6;   // 32 floats per thread
        const float* src = x + (size_t)(r0 + e) * C + t2 * 32;
        int cbase = t2 * 32;
        #pragma unroll
        for (int i = 0; i < 8; i++) {
            float4 v = *(const float4*)(src + i * 4);
            int c = cbase + i * 4;
            bufA[(c + 0) * SROW + e] = v.x;
            bufA[(c + 1) * SROW + e] = v.y;
            bufA[(c + 2) * SROW + e] = v.z;
            bufA[(c + 3) * SROW + e] = v.w;
        }
    }
    __syncthreads();
    layer_mlp<C, C, false>(W, b, bufA, bufB, wt, tid);
    __syncthreads();
    // Write back row-major
    #pragma unroll
    for (int j = 0; j < 32; j++) {
        int f = tid + j * NTHR;          // 0..12287
        int e = f / C, c = f % C;
        g_xf[(size_t)(r0 + e) * C + c] = bufB[(size_t)c * SROW + e];
    }
}

// ---------------- zero accumulators ----------------
__global__ void k_zero() {
    int idx = blockIdx.x * blockDim.x + threadIdx.x;
    int stride = gridDim.x * blockDim.x;
    for (int i = idx; i < NQ * C; i += stride) g_seg[i] = 0.0f;
    for (int i = idx; i < NQ; i += stride) g_cnt[i] = 0;
}

// ---------------- fused edge MLP + segment sum ----------------
__global__ void __launch_bounds__(NTHR, 1) k_edges(const void* __restrict__ Eg,
    const float* __restrict__ W0, const float* __restrict__ b0,
    const float* __restrict__ W1, const float* __restrict__ b1,
    const float* __restrict__ W2, const float* __restrict__ b2)
{
    extern __shared__ float sm[];
    float* bufA = sm;                     // [384][SROW]
    float* bufB = bufA + C2 * SROW;       // [384][SROW]
    float* wt   = bufB + C2 * SROW;       // KT*192
    int* qs = (int*)(wt + KT * 192);      // [64]
    int tid = threadIdx.x;
    int e0 = blockIdx.x * TILE;
    // Gather: 6 threads/edge, 64 floats each (first 192 cols = xf[g], next 192 = qe[q])
    {
        int e = tid / 6, t2 = tid % 6;
        int q, g;
        load_edge(Eg, e0 + e, q, g);
        if (t2 == 0) qs[e] = q;
        const float* src = (t2 < 3) ? (g_xf + (size_t)g * C + t2 * 64)
                                    : (g_qe + (size_t)q * C + (t2 - 3) * 64);
        int cbase = t2 * 64;
        #pragma unroll
        for (int i = 0; i < 16; i++) {
            float4 v = *(const float4*)(src + i * 4);
            int c = cbase + i * 4;
            bufA[(c + 0) * SROW + e] = v.x;
            bufA[(c + 1) * SROW + e] = v.y;
            bufA[(c + 2) * SROW + e] = v.z;
            bufA[(c + 3) * SROW + e] = v.w;
        }
    }
    __syncthreads();
    layer_mlp<C2, C2, true >(W0, b0, bufA, bufB, wt, tid);
    __syncthreads();
    layer_mlp<C2, C2, true >(W1, b1, bufB, bufA, wt, tid);
    __syncthreads();
    layer_mlp<C2, C,  false>(W2, b2, bufA, bufB, wt, tid);
    __syncthreads();
    // Segment-sum: qidx is globally sorted -> runs are contiguous within tile.
    if (tid < C) {
        int c = tid;
        int cur = qs[0];
        float s = bufB[(size_t)c * SROW + 0];
        for (int e = 1; e < TILE; e++) {
            int q = qs[e];
            float v = bufB[(size_t)c * SROW + e];
            if (q == cur) s += v;
            else { atomicAdd(&g_seg[(size_t)cur * C + c], s); cur = q; s = v; }
        }
        atomicAdd(&g_seg[(size_t)cur * C + c], s);
    } else if (tid == C) {
        int cur = qs[0]; int n = 1;
        for (int e = 1; e < TILE; e++) {
            int q = qs[e];
            if (q == cur) n++;
            else { atomicAdd(&g_cnt[cur], n); cur = q; n = 1; }
        }
        atomicAdd(&g_cnt[cur], n);
    }
}

// ---------------- prediction head ----------------
__global__ void __launch_bounds__(NTHR, 1) k_pred(const float* __restrict__ Wp0,
                                                  const float* __restrict__ bp0,
                                                  const float* __restrict__ Wp1,
                                                  const float* __restrict__ bp1,
                                                  float* __restrict__ out)
{
    extern __shared__ float sm[];
    float* bufA = sm;
    float* bufB = bufA + C * SROW;
    float* wt   = bufB + C * SROW;
    int tid = threadIdx.x;
    int q0 = blockIdx.x * TILE;
    {
        int e = tid / 6, t2 = tid % 6;
        int q = q0 + e;
        float inv = 1.0f / fmaxf((float)g_cnt[q], 1.0f);
        const float* src = g_seg + (size_t)q * C + t2 * 32;
        int cbase = t2 * 32;
        #pragma unroll
        for (int i = 0; i < 8; i++) {
            float4 v = *(const float4*)(src + i * 4);
            int c = cbase + i * 4;
            bufA[(c + 0) * SROW + e] = v.x * inv;
            bufA[(c + 1) * SROW + e] = v.y * inv;
            bufA[(c + 2) * SROW + e] = v.z * inv;
            bufA[(c + 3) * SROW + e] = v.w * inv;
        }
    }
    __syncthreads();
    layer_mlp<C, C, true>(Wp0, bp0, bufA, bufB, wt, tid);
    __syncthreads();
    if (tid < 256) {
        int q = tid >> 2, o = tid & 3;
        float s = bp1[o];
        #pragma unroll 8
        for (int k = 0; k < C; k++)
            s += bufB[(size_t)k * SROW + q] * Wp1[k * 4 + o];
        out[(size_t)(q0 + q) * 4 + o] = s;
    }
}

extern "C" void kernel_launch(void* const* d_in, const int* in_sizes, int n_in,
                              void* d_out, int out_size)
{
    const float* x       = (const float*)d_in[0];
    const float* qp      = (const float*)d_in[1];
    const void*  E       = d_in[2];
    const float* proj_w  = (const float*)d_in[3];
    const float* proj_b  = (const float*)d_in[4];
    const float* m0w     = (const float*)d_in[5];
    const float* m0b     = (const float*)d_in[6];
    const float* m1w     = (const float*)d_in[7];
    const float* m1b     = (const float*)d_in[8];
    const float* m2w     = (const float*)d_in[9];
    const float* m2b     = (const float*)d_in[10];
    const float* p0w     = (const float*)d_in[11];
    const float* p0b     = (const float*)d_in[12];
    const float* p1w     = (const float*)d_in[13];
    const float* p1b     = (const float*)d_in[14];
    float* out = (float*)d_out;

    const int SM_EDGE  = (2 * C2 * SROW + KT * 192) * 4 + TILE * 4;  // 227,584 B
    const int SM_SMALL = (2 * C * SROW + KT * 192) * 4;              // 125,952 B

    cudaFuncSetAttribute(k_edges, cudaFuncAttributeMaxDynamicSharedMemorySize, SM_EDGE);
    cudaFuncSetAttribute(k_proj,  cudaFuncAttributeMaxDynamicSharedMemorySize, SM_SMALL);
    cudaFuncSetAttribute(k_pred,  cudaFuncAttributeMaxDynamicSharedMemorySize, SM_SMALL);

    k_detect<<<1, 32>>>((const int*)E);
    k_embed<<<NQ, 96>>>(qp);
    k_proj<<<SGRID / TILE, NTHR, SM_SMALL>>>(x, proj_w, proj_b);
    k_zero<<<2048, 256>>>();
    k_edges<<<NEDGE / TILE, NTHR, SM_EDGE>>>(E, m0w, m0b, m1w, m1b, m2w, m2b);
    k_pred<<<NQ / TILE, NTHR, SM_SMALL>>>(p0w, p0b, p1w, p1b, out);
}